// round 4
// baseline (speedup 1.0000x reference)
#include <cuda_runtime.h>
#include <cstdint>

// x:               [256, 30, 30, 512] f32   = [230400 pixels][128 float4]
// pattern_indices: [230400]           int32 (harness downcasts int64)
// spatial_pe:      [900][64]          float4
// pattern_pe:      [64][64]           float4
// out = x + concat(spatial_pe[hw], pattern_pe[idx & 63]) per pixel
//
// blockDim=128, each block handles 8 consecutive pixels.
// Thread t owns channel-float4 d4 = t for pixels pix0..pix0+7:
//   - d4 constant per thread -> spatial/pattern branch warp-uniform
//   - 8 independent x loads front-batched -> deep MLP hides DRAM latency
//   - pattern index loads issued FIRST so the idx->table chain overlaps x loads
//   - single %900 per thread, wrap by conditional subtract

#define HW        900
#define PIX_TOTAL (256 * 900)       // 230400
#define PIX_PER_BLOCK 8

__global__ void __launch_bounds__(128, 6)
pe_add_kernel(const float4* __restrict__ x,
              const int*    __restrict__ pattern_indices,
              const float4* __restrict__ spatial_pe,   // [900*64]
              const float4* __restrict__ pattern_pe,   // [64*64]
              float4*       __restrict__ out)
{
    const int t    = threadIdx.x;             // 0..127 == d4
    const int pix0 = blockIdx.x * PIX_PER_BLOCK;
    const int base = pix0 * 128 + t;          // < 29.5M, fits int32

    const bool is_pattern = (t >= 64);

    // Start the dependent gather chain early: pattern-index loads first.
    int idx[PIX_PER_BLOCK];
    if (is_pattern) {
#pragma unroll
        for (int k = 0; k < PIX_PER_BLOCK; k++)
            idx[k] = pattern_indices[pix0 + k];
    }

    // Front-batch the 8 streaming x loads (independent, warp-coalesced 512B).
    float4 xv[PIX_PER_BLOCK];
#pragma unroll
    for (int k = 0; k < PIX_PER_BLOCK; k++)
        xv[k] = x[base + k * 128];

    float4 pe[PIX_PER_BLOCK];
    if (!is_pattern) {
        // spatial half: hw = pixel % 900, consecutive pixels -> hw0+k with wrap
        int hw0 = pix0 % HW;
#pragma unroll
        for (int k = 0; k < PIX_PER_BLOCK; k++) {
            int hw = hw0 + k;
            if (hw >= HW) hw -= HW;
            pe[k] = spatial_pe[hw * 64 + t];
        }
    } else {
#pragma unroll
        for (int k = 0; k < PIX_PER_BLOCK; k++)
            pe[k] = pattern_pe[(idx[k] & 63) * 64 + (t - 64)];
    }

#pragma unroll
    for (int k = 0; k < PIX_PER_BLOCK; k++) {
        xv[k].x += pe[k].x;
        xv[k].y += pe[k].y;
        xv[k].z += pe[k].z;
        xv[k].w += pe[k].w;
        out[base + k * 128] = xv[k];
    }
}

extern "C" void kernel_launch(void* const* d_in, const int* in_sizes, int n_in,
                              void* d_out, int out_size)
{
    const float4* x   = (const float4*)d_in[0];
    const int*    pid = (const int*)d_in[1];
    const float4* spe = (const float4*)d_in[2];
    const float4* ppe = (const float4*)d_in[3];
    float4*       out = (float4*)d_out;

    const int grid = PIX_TOTAL / PIX_PER_BLOCK;   // 28800 blocks
    pe_add_kernel<<<grid, 128>>>(x, pid, spe, ppe, out);
}

// round 5
// speedup vs baseline: 1.0032x; 1.0032x over previous
#include <cuda_runtime.h>
#include <cstdint>

// x:               [256, 30, 30, 512] f32   = [230400 pixels][128 float4]
// pattern_indices: [230400]           int32 (harness downcasts int64)
// spatial_pe:      [900][64]          float4
// pattern_pe:      [64][64]           float4
// out = x + concat(spatial_pe[hw], pattern_pe[idx & 63]) per pixel
//
// blockDim=128, each block handles 4 consecutive pixels (R3 geometry — R4
// showed deeper batching is neutral; latency already hidden).
// Cache policy: x/out are touch-once streams -> __ldcs/__stcs (evict-first),
// tables are hot -> __ldg, so L2 keeps spatial_pe/pattern_pe/indices resident.

#define HW        900
#define PIX_TOTAL (256 * 900)       // 230400
#define PIX_PER_BLOCK 4

__device__ __forceinline__ float4 ldcs_f4(const float4* p) {
    return __ldcs(p);
}

__global__ void __launch_bounds__(128)
pe_add_kernel(const float4* __restrict__ x,
              const int*    __restrict__ pattern_indices,
              const float4* __restrict__ spatial_pe,   // [900*64]
              const float4* __restrict__ pattern_pe,   // [64*64]
              float4*       __restrict__ out)
{
    const int t    = threadIdx.x;             // 0..127 == d4
    const int pix0 = blockIdx.x * PIX_PER_BLOCK;
    const int base = pix0 * 128 + t;          // < 29.5M, fits int32

    const bool is_pattern = (t >= 64);

    // Start the dependent gather chain early: pattern-index loads first.
    int idx[PIX_PER_BLOCK];
    if (is_pattern) {
#pragma unroll
        for (int k = 0; k < PIX_PER_BLOCK; k++)
            idx[k] = __ldg(&pattern_indices[pix0 + k]);
    }

    // Front-batch the 4 streaming x loads (independent, warp-coalesced 512B),
    // evict-first so they don't displace the PE tables in L2.
    float4 xv[PIX_PER_BLOCK];
#pragma unroll
    for (int k = 0; k < PIX_PER_BLOCK; k++)
        xv[k] = ldcs_f4(&x[base + k * 128]);

    float4 pe[PIX_PER_BLOCK];
    if (!is_pattern) {
        // spatial half: hw = pixel % 900, consecutive pixels -> hw0+k with wrap
        int hw0 = pix0 % HW;
#pragma unroll
        for (int k = 0; k < PIX_PER_BLOCK; k++) {
            int hw = hw0 + k;
            if (hw >= HW) hw -= HW;
            pe[k] = __ldg(&spatial_pe[hw * 64 + t]);
        }
    } else {
#pragma unroll
        for (int k = 0; k < PIX_PER_BLOCK; k++)
            pe[k] = __ldg(&pattern_pe[(idx[k] & 63) * 64 + (t - 64)]);
    }

#pragma unroll
    for (int k = 0; k < PIX_PER_BLOCK; k++) {
        xv[k].x += pe[k].x;
        xv[k].y += pe[k].y;
        xv[k].z += pe[k].z;
        xv[k].w += pe[k].w;
        __stcs(&out[base + k * 128], xv[k]);
    }
}

extern "C" void kernel_launch(void* const* d_in, const int* in_sizes, int n_in,
                              void* d_out, int out_size)
{
    const float4* x   = (const float4*)d_in[0];
    const int*    pid = (const int*)d_in[1];
    const float4* spe = (const float4*)d_in[2];
    const float4* ppe = (const float4*)d_in[3];
    float4*       out = (float4*)d_out;

    const int grid = PIX_TOTAL / PIX_PER_BLOCK;   // 57600 blocks
    pe_add_kernel<<<grid, 128>>>(x, pid, spe, ppe, out);
}